// round 4
// baseline (speedup 1.0000x reference)
#include <cuda_runtime.h>
#include <math.h>

#define NRAYS 16384
#define NSEG 8
#define PTS_PER_SEG 32
#define IMG_DIM 128
#define NVOX (128 * 128 * 128)

// -------- device scratch (no allocations allowed) --------
// Declared as float4 to guarantee 16B alignment for STG.128 in pack_kernel.
// Logically: float2 pairs (feature, density*0.1), NVOX entries, 16MB.
__device__ float4 g_pack4[NVOX / 2];
__device__ float g_acc[NSEG * NRAYS];
__device__ float g_prodv[NSEG * NRAYS];
__device__ float g_gray[NRAYS];
// Initializers are load-bearing: first kernel invocation reads these, and the
// end of combine_finalize_kernel resets them to the same values for replay.
__device__ double g_sum = 0.0, g_sumsq = 0.0;
__device__ unsigned g_minkey = 0xFFFFFFFFu;
__device__ unsigned g_maxkey = 0u;
__device__ unsigned g_count = 0u;

// -------- ordered-float key for atomicMin/Max --------
__device__ __forceinline__ unsigned fkey(float f) {
    unsigned u = __float_as_uint(f);
    return (u & 0x80000000u) ? ~u : (u | 0x80000000u);
}
__device__ __forceinline__ float funkey(unsigned k) {
    return (k & 0x80000000u) ? __uint_as_float(k & 0x7FFFFFFFu)
                             : __uint_as_float(~k);
}

// -------- pack both volumes into interleaved float2 (density prescaled) ----
// 524288 threads, each handles 4 voxels via float4 loads / 2 float4 stores
__global__ void __launch_bounds__(256)
pack_kernel(const float4* __restrict__ img, const float4* __restrict__ opa) {
    int i = blockIdx.x * blockDim.x + threadIdx.x;  // 0..524287
    float4 f = __ldg(img + i);
    float4 d = __ldg(opa + i);
    g_pack4[i * 2 + 0] = make_float4(f.x, d.x * 0.1f, f.y, d.y * 0.1f);
    g_pack4[i * 2 + 1] = make_float4(f.z, d.z * 0.1f, f.w, d.w * 0.1f);
}

// -------- trilinear sample of packed volume (zero padding outside) --------
__device__ __forceinline__ void tri_sample(float fx, float fy, float fz,
                                           float& f, float& d) {
    float x0 = floorf(fx), y0 = floorf(fy), z0 = floorf(fz);
    int ix = (int)x0, iy = (int)y0, iz = (int)z0;
    float wx = fx - x0, wy = fy - y0, wz = fz - z0;
    f = 0.f;
    d = 0.f;
    const float2* __restrict__ pack = (const float2*)g_pack4;
#pragma unroll
    for (int dz = 0; dz < 2; dz++) {
#pragma unroll
        for (int dy = 0; dy < 2; dy++) {
#pragma unroll
            for (int dx = 0; dx < 2; dx++) {
                int X = ix + dx, Y = iy + dy, Z = iz + dz;
                if ((unsigned)X < 128u && (unsigned)Y < 128u && (unsigned)Z < 128u) {
                    float wt = (dx ? wx : 1.f - wx) * (dy ? wy : 1.f - wy) *
                               (dz ? wz : 1.f - wz);
                    int idx = (Z << 14) + (Y << 7) + X;
                    float2 v = __ldg(pack + idx);
                    f += wt * v.x;
                    d += wt * v.y;
                }
            }
        }
    }
}

// -------- per-(ray,segment) rendering --------
// grid: (NSEG, 128 rows), block: 128 threads (one per pixel column w)
__global__ void __launch_bounds__(128)
render_kernel(const float* __restrict__ Rm, const float* __restrict__ Tv) {
    int w = threadIdx.x;
    int seg = blockIdx.x;
    int h = blockIdx.y;

    // NDC grid: xs = linspace(1,-1,128) over w; ys likewise over h
    float gx = 1.f + (float)w * (-2.f / 127.f);
    float gy = 1.f + (float)h * (-2.f / 127.f);
    const float INV_FOCAL = 1.f / 1.7320508f;
    float dc0 = gx * INV_FOCAL, dc1 = gy * INV_FOCAL;  // dc2 = 1

    float R00 = Rm[0], R01 = Rm[1], R02 = Rm[2];
    float R10 = Rm[3], R11 = Rm[4], R12 = Rm[5];
    float R20 = Rm[6], R21 = Rm[7], R22 = Rm[8];
    float T0 = Tv[0], T1 = Tv[1], T2 = Tv[2];

    // dirs_world[j] = sum_i dirs_cam[i] * R[j][i]
    float dwx = dc0 * R00 + dc1 * R01 + R02;
    float dwy = dc0 * R10 + dc1 * R11 + R12;
    float dwz = dc0 * R20 + dc1 * R21 + R22;
    // origin[j] = sum_i (-T[i]) * R[j][i]
    float ox = -(T0 * R00 + T1 * R01 + T2 * R02);
    float oy = -(T0 * R10 + T1 * R11 + T2 * R12);
    float oz = -(T0 * R20 + T1 * R21 + T2 * R22);

    // sample coord: fx = ((pos/half_extent)+1)*0.5*127 = pos*s + 63.5
    const float HE = 1.48828125f;  // (3/128)*127/2
    const float s = 63.5f / HE;
    float ax = dwx * s, bx = ox * s + 63.5f;
    float ay = dwy * s, by = oy * s + 63.5f;
    float az = dwz * s, bz = oz * s + 63.5f;

    float Tt = 1.f, acc = 0.f;
    int p0 = seg * PTS_PER_SEG;

#pragma unroll
    for (int g = 0; g < PTS_PER_SEG / 4; g++) {
        float fv[4], dv[4];
#pragma unroll
        for (int k = 0; k < 4; k++) {
            int p = p0 + g * 4 + k;
            float depth = 2.f + (float)p * (4.f / 255.f);
            tri_sample(ax * depth + bx, ay * depth + by, az * depth + bz,
                       fv[k], dv[k]);
        }
#pragma unroll
        for (int k = 0; k < 4; k++) {
            // (1.0 + 1e-10) == 1.0f in fp32 (matches JAX fp32 trace)
            acc += fv[k] * dv[k] * Tt;
            Tt *= (1.f - dv[k]);
        }
    }

    int r = h * 128 + w;
    g_acc[seg * NRAYS + r] = acc;
    g_prodv[seg * NRAYS + r] = Tt;
}

// -------- fused: combine segments + global stats + normalize + reset ------
// grid: 64 blocks x 256 threads; last-arriving block finalizes.
__global__ void __launch_bounds__(256) combine_finalize_kernel(float* __restrict__ out) {
    int r = blockIdx.x * blockDim.x + threadIdx.x;
    float gray = 0.f;
    float Tt = 1.f;
#pragma unroll
    for (int s2 = 0; s2 < NSEG; s2++) {
        gray += g_acc[s2 * NRAYS + r] * Tt;
        Tt *= g_prodv[s2 * NRAYS + r];
    }
    g_gray[r] = gray;

    // block reduction: sum, sumsq (double), min, max
    double sm = (double)gray;
    double sq = (double)gray * (double)gray;
    float mn = gray, mx = gray;
#pragma unroll
    for (int off = 16; off > 0; off >>= 1) {
        sm += __shfl_down_sync(0xFFFFFFFFu, sm, off);
        sq += __shfl_down_sync(0xFFFFFFFFu, sq, off);
        mn = fminf(mn, __shfl_down_sync(0xFFFFFFFFu, mn, off));
        mx = fmaxf(mx, __shfl_down_sync(0xFFFFFFFFu, mx, off));
    }
    __shared__ double s_sm[8], s_sq[8];
    __shared__ float s_mn[8], s_mx[8];
    int lane = threadIdx.x & 31, wid = threadIdx.x >> 5;
    if (lane == 0) {
        s_sm[wid] = sm;
        s_sq[wid] = sq;
        s_mn[wid] = mn;
        s_mx[wid] = mx;
    }
    __syncthreads();
    if (wid == 0) {
        sm = (lane < 8) ? s_sm[lane] : 0.0;
        sq = (lane < 8) ? s_sq[lane] : 0.0;
        mn = (lane < 8) ? s_mn[lane] : 3.0e38f;
        mx = (lane < 8) ? s_mx[lane] : -3.0e38f;
#pragma unroll
        for (int off = 4; off > 0; off >>= 1) {
            sm += __shfl_down_sync(0xFFFFFFFFu, sm, off);
            sq += __shfl_down_sync(0xFFFFFFFFu, sq, off);
            mn = fminf(mn, __shfl_down_sync(0xFFFFFFFFu, mn, off));
            mx = fmaxf(mx, __shfl_down_sync(0xFFFFFFFFu, mx, off));
        }
        if (lane == 0) {
            atomicAdd(&g_sum, sm);
            atomicAdd(&g_sumsq, sq);
            atomicMin(&g_minkey, fkey(mn));
            atomicMax(&g_maxkey, fkey(mx));
        }
    }

    // last-block-arrives: finalize + reset scratch for next graph replay
    __threadfence();
    __shared__ bool is_last;
    __shared__ float sh_mean, sh_inv, sh_stmin, sh_stmax;
    if (threadIdx.x == 0) {
        unsigned c = atomicAdd(&g_count, 1u);
        is_last = (c == 63u);
    }
    __syncthreads();
    if (!is_last) return;

    if (threadIdx.x == 0) {
        double sum = *(volatile double*)&g_sum;
        double sumsq = *(volatile double*)&g_sumsq;
        unsigned mnk = *(volatile unsigned*)&g_minkey;
        unsigned mxk = *(volatile unsigned*)&g_maxkey;
        double mean = sum / 16384.0;
        double var = (sumsq - sum * sum / 16384.0) / 16383.0;
        float stddev = (float)sqrt(var > 0.0 ? var : 0.0);
        float gmin = funkey(mnk), gmax = funkey(mxk);
        float fmean = (float)mean;
        float inv = 1.f / (stddev + 1e-8f);
        sh_mean = fmean;
        sh_inv = inv;
        sh_stmin = (gmin - fmean) * inv;
        sh_stmax = (gmax - fmean) * inv;
        // reset scratch to module-load state for the next replay
        g_sum = 0.0;
        g_sumsq = 0.0;
        g_minkey = 0xFFFFFFFFu;
        g_maxkey = 0u;
        g_count = 0u;
    }
    __syncthreads();

    float fmean = sh_mean, inv = sh_inv;
    float stmin = sh_stmin, stmax = sh_stmax;
    float rng = 1.f / (stmax - stmin + 1e-8f);
    // out layout [1,1,W,H]: out[w*128+h] = gray(h,w)
    for (int o = threadIdx.x; o < NRAYS; o += 256) {
        int w = o >> 7, h = o & 127;
        float st = (g_gray[h * 128 + w] - fmean) * inv;
        out[o] = (st - stmin + 1e-8f) * rng;
    }
}

extern "C" void kernel_launch(void* const* d_in, const int* in_sizes, int n_in,
                              void* d_out, int out_size) {
    const float* img = (const float*)d_in[0];  // image3d [1,1,128,128,128]
    const float* opa = (const float*)d_in[1];  // opacity  [1,1,128,128,128]
    const float* Rm = (const float*)d_in[2];   // R [1,3,3]
    const float* Tv = (const float*)d_in[3];   // T [1,3]
    float* out = (float*)d_out;                // [1,1,128,128]

    pack_kernel<<<NVOX / 4 / 256, 256>>>((const float4*)img, (const float4*)opa);
    render_kernel<<<dim3(NSEG, IMG_DIM), 128>>>(Rm, Tv);
    combine_finalize_kernel<<<64, 256>>>(out);
}

// round 5
// speedup vs baseline: 1.5810x; 1.5810x over previous
#include <cuda_runtime.h>
#include <math.h>

#define NRAYS 16384
#define NSEG 8
#define PTS_PER_SEG 32
#define IMG_DIM 128

// -------- device scratch (no allocations allowed) --------
__device__ float g_acc[NSEG * NRAYS];
__device__ float g_prodv[NSEG * NRAYS];
__device__ float g_gray[NRAYS];
// Initializers are load-bearing: the first invocation reads these, and the
// end of combine_finalize_kernel resets them to the same values for replay.
__device__ double g_sum = 0.0, g_sumsq = 0.0;
__device__ unsigned g_minkey = 0xFFFFFFFFu;
__device__ unsigned g_maxkey = 0u;
__device__ unsigned g_count = 0u;

// -------- ordered-float key for atomicMin/Max --------
__device__ __forceinline__ unsigned fkey(float f) {
    unsigned u = __float_as_uint(f);
    return (u & 0x80000000u) ? ~u : (u | 0x80000000u);
}
__device__ __forceinline__ float funkey(unsigned k) {
    return (k & 0x80000000u) ? __uint_as_float(k & 0x7FFFFFFFu)
                             : __uint_as_float(~k);
}

// -------- trilinear sample of both volumes (zero padding outside) --------
__device__ __forceinline__ void tri_sample(const float* __restrict__ img,
                                           const float* __restrict__ opa,
                                           float fx, float fy, float fz,
                                           float& f, float& d) {
    float x0 = floorf(fx), y0 = floorf(fy), z0 = floorf(fz);
    int ix = (int)x0, iy = (int)y0, iz = (int)z0;
    float wx = fx - x0, wy = fy - y0, wz = fz - z0;
    f = 0.f;
    d = 0.f;
#pragma unroll
    for (int dz = 0; dz < 2; dz++) {
#pragma unroll
        for (int dy = 0; dy < 2; dy++) {
#pragma unroll
            for (int dx = 0; dx < 2; dx++) {
                int X = ix + dx, Y = iy + dy, Z = iz + dz;
                if ((unsigned)X < 128u && (unsigned)Y < 128u && (unsigned)Z < 128u) {
                    float wt = (dx ? wx : 1.f - wx) * (dy ? wy : 1.f - wy) *
                               (dz ? wz : 1.f - wz);
                    int idx = (Z << 14) + (Y << 7) + X;
                    f += wt * __ldg(img + idx);
                    d += wt * __ldg(opa + idx);
                }
            }
        }
    }
}

// -------- per-(ray,segment) rendering --------
// grid: (NSEG, 128 rows), block: 128 threads (one per pixel column w)
__global__ void __launch_bounds__(128)
render_kernel(const float* __restrict__ img, const float* __restrict__ opa,
              const float* __restrict__ Rm, const float* __restrict__ Tv) {
    int w = threadIdx.x;
    int seg = blockIdx.x;
    int h = blockIdx.y;

    // NDC grid: xs = linspace(1,-1,128) over w; ys likewise over h
    float gx = 1.f + (float)w * (-2.f / 127.f);
    float gy = 1.f + (float)h * (-2.f / 127.f);
    const float INV_FOCAL = 1.f / 1.7320508f;
    float dc0 = gx * INV_FOCAL, dc1 = gy * INV_FOCAL;  // dc2 = 1

    float R00 = Rm[0], R01 = Rm[1], R02 = Rm[2];
    float R10 = Rm[3], R11 = Rm[4], R12 = Rm[5];
    float R20 = Rm[6], R21 = Rm[7], R22 = Rm[8];
    float T0 = Tv[0], T1 = Tv[1], T2 = Tv[2];

    // dirs_world[j] = sum_i dirs_cam[i] * R[j][i]
    float dwx = dc0 * R00 + dc1 * R01 + R02;
    float dwy = dc0 * R10 + dc1 * R11 + R12;
    float dwz = dc0 * R20 + dc1 * R21 + R22;
    // origin[j] = sum_i (-T[i]) * R[j][i]
    float ox = -(T0 * R00 + T1 * R01 + T2 * R02);
    float oy = -(T0 * R10 + T1 * R11 + T2 * R12);
    float oz = -(T0 * R20 + T1 * R21 + T2 * R22);

    // sample coord: fx = ((pos/half_extent)+1)*0.5*127 = pos*s + 63.5
    const float HE = 1.48828125f;  // (3/128)*127/2
    const float s = 63.5f / HE;
    float ax = dwx * s, bx = ox * s + 63.5f;
    float ay = dwy * s, by = oy * s + 63.5f;
    float az = dwz * s, bz = oz * s + 63.5f;

    float Tt = 1.f, acc = 0.f;
    int p0 = seg * PTS_PER_SEG;

#pragma unroll
    for (int g = 0; g < PTS_PER_SEG / 4; g++) {
        float fv[4], dv[4];
#pragma unroll
        for (int k = 0; k < 4; k++) {
            int p = p0 + g * 4 + k;
            float depth = 2.f + (float)p * (4.f / 255.f);
            tri_sample(img, opa, ax * depth + bx, ay * depth + by,
                       az * depth + bz, fv[k], dv[k]);
            dv[k] *= 0.1f;  // densities = opacity * SCALING
        }
#pragma unroll
        for (int k = 0; k < 4; k++) {
            // (1.0 + 1e-10) == 1.0f in fp32 (matches JAX fp32 trace)
            acc += fv[k] * dv[k] * Tt;
            Tt *= (1.f - dv[k]);
        }
    }

    int r = h * 128 + w;
    g_acc[seg * NRAYS + r] = acc;
    g_prodv[seg * NRAYS + r] = Tt;
}

// -------- fused: combine segments + global stats + normalize + reset ------
// grid: 64 blocks x 256 threads; last-arriving block finalizes.
__global__ void __launch_bounds__(256) combine_finalize_kernel(float* __restrict__ out) {
    int r = blockIdx.x * blockDim.x + threadIdx.x;
    float gray = 0.f;
    float Tt = 1.f;
#pragma unroll
    for (int s2 = 0; s2 < NSEG; s2++) {
        gray += g_acc[s2 * NRAYS + r] * Tt;
        Tt *= g_prodv[s2 * NRAYS + r];
    }
    g_gray[r] = gray;

    // block reduction: sum, sumsq (double), min, max
    double sm = (double)gray;
    double sq = (double)gray * (double)gray;
    float mn = gray, mx = gray;
#pragma unroll
    for (int off = 16; off > 0; off >>= 1) {
        sm += __shfl_down_sync(0xFFFFFFFFu, sm, off);
        sq += __shfl_down_sync(0xFFFFFFFFu, sq, off);
        mn = fminf(mn, __shfl_down_sync(0xFFFFFFFFu, mn, off));
        mx = fmaxf(mx, __shfl_down_sync(0xFFFFFFFFu, mx, off));
    }
    __shared__ double s_sm[8], s_sq[8];
    __shared__ float s_mn[8], s_mx[8];
    int lane = threadIdx.x & 31, wid = threadIdx.x >> 5;
    if (lane == 0) {
        s_sm[wid] = sm;
        s_sq[wid] = sq;
        s_mn[wid] = mn;
        s_mx[wid] = mx;
    }
    __syncthreads();
    if (wid == 0) {
        sm = (lane < 8) ? s_sm[lane] : 0.0;
        sq = (lane < 8) ? s_sq[lane] : 0.0;
        mn = (lane < 8) ? s_mn[lane] : 3.0e38f;
        mx = (lane < 8) ? s_mx[lane] : -3.0e38f;
#pragma unroll
        for (int off = 4; off > 0; off >>= 1) {
            sm += __shfl_down_sync(0xFFFFFFFFu, sm, off);
            sq += __shfl_down_sync(0xFFFFFFFFu, sq, off);
            mn = fminf(mn, __shfl_down_sync(0xFFFFFFFFu, mn, off));
            mx = fmaxf(mx, __shfl_down_sync(0xFFFFFFFFu, mx, off));
        }
        if (lane == 0) {
            atomicAdd(&g_sum, sm);
            atomicAdd(&g_sumsq, sq);
            atomicMin(&g_minkey, fkey(mn));
            atomicMax(&g_maxkey, fkey(mx));
        }
    }

    // last-block-arrives: finalize + reset scratch for next graph replay
    __threadfence();
    __shared__ bool is_last;
    __shared__ float sh_mean, sh_inv, sh_stmin, sh_stmax;
    if (threadIdx.x == 0) {
        unsigned c = atomicAdd(&g_count, 1u);
        is_last = (c == 63u);
    }
    __syncthreads();
    if (!is_last) return;

    if (threadIdx.x == 0) {
        double sum = *(volatile double*)&g_sum;
        double sumsq = *(volatile double*)&g_sumsq;
        unsigned mnk = *(volatile unsigned*)&g_minkey;
        unsigned mxk = *(volatile unsigned*)&g_maxkey;
        double mean = sum / 16384.0;
        double var = (sumsq - sum * sum / 16384.0) / 16383.0;
        float stddev = (float)sqrt(var > 0.0 ? var : 0.0);
        float gmin = funkey(mnk), gmax = funkey(mxk);
        float fmean = (float)mean;
        float inv = 1.f / (stddev + 1e-8f);
        sh_mean = fmean;
        sh_inv = inv;
        sh_stmin = (gmin - fmean) * inv;
        sh_stmax = (gmax - fmean) * inv;
        // reset scratch to module-load state for the next replay
        g_sum = 0.0;
        g_sumsq = 0.0;
        g_minkey = 0xFFFFFFFFu;
        g_maxkey = 0u;
        g_count = 0u;
    }
    __syncthreads();

    float fmean = sh_mean, inv = sh_inv;
    float stmin = sh_stmin, stmax = sh_stmax;
    float rng = 1.f / (stmax - stmin + 1e-8f);
    // out layout [1,1,W,H]: out[w*128+h] = gray(h,w)
    for (int o = threadIdx.x; o < NRAYS; o += 256) {
        int w = o >> 7, h = o & 127;
        float st = (g_gray[h * 128 + w] - fmean) * inv;
        out[o] = (st - stmin + 1e-8f) * rng;
    }
}

extern "C" void kernel_launch(void* const* d_in, const int* in_sizes, int n_in,
                              void* d_out, int out_size) {
    const float* img = (const float*)d_in[0];  // image3d [1,1,128,128,128]
    const float* opa = (const float*)d_in[1];  // opacity  [1,1,128,128,128]
    const float* Rm = (const float*)d_in[2];   // R [1,3,3]
    const float* Tv = (const float*)d_in[3];   // T [1,3]
    float* out = (float*)d_out;                // [1,1,128,128]

    render_kernel<<<dim3(NSEG, IMG_DIM), 128>>>(img, opa, Rm, Tv);
    combine_finalize_kernel<<<64, 256>>>(out);
}

// round 6
// speedup vs baseline: 2.0507x; 1.2971x over previous
#include <cuda_runtime.h>
#include <math.h>

#define NRAYS 16384
#define NSEG 16
#define PTS_PER_SEG 16
#define IMG_DIM 128

// -------- device scratch (no allocations allowed) --------
__device__ float g_acc[NSEG * NRAYS];
__device__ float g_prodv[NSEG * NRAYS];
__device__ float g_gray[NRAYS];
// Initializers are load-bearing: the first invocation reads these, and the
// end of combine_finalize_kernel resets them to the same values for replay.
__device__ double g_sum = 0.0, g_sumsq = 0.0;
__device__ unsigned g_minkey = 0xFFFFFFFFu;
__device__ unsigned g_maxkey = 0u;
__device__ unsigned g_count = 0u;

// -------- ordered-float key for atomicMin/Max --------
__device__ __forceinline__ unsigned fkey(float f) {
    unsigned u = __float_as_uint(f);
    return (u & 0x80000000u) ? ~u : (u | 0x80000000u);
}
__device__ __forceinline__ float funkey(unsigned k) {
    return (k & 0x80000000u) ? __uint_as_float(k & 0x7FFFFFFFu)
                             : __uint_as_float(~k);
}

// -------- trilinear sample of both volumes (zero padding outside) --------
__device__ __forceinline__ void tri_sample(const float* __restrict__ img,
                                           const float* __restrict__ opa,
                                           float fx, float fy, float fz,
                                           float& f, float& d) {
    float x0 = floorf(fx), y0 = floorf(fy), z0 = floorf(fz);
    int ix = (int)x0, iy = (int)y0, iz = (int)z0;
    float wx = fx - x0, wy = fy - y0, wz = fz - z0;
    f = 0.f;
    d = 0.f;
#pragma unroll
    for (int dz = 0; dz < 2; dz++) {
#pragma unroll
        for (int dy = 0; dy < 2; dy++) {
#pragma unroll
            for (int dx = 0; dx < 2; dx++) {
                int X = ix + dx, Y = iy + dy, Z = iz + dz;
                if ((unsigned)X < 128u && (unsigned)Y < 128u && (unsigned)Z < 128u) {
                    float wt = (dx ? wx : 1.f - wx) * (dy ? wy : 1.f - wy) *
                               (dz ? wz : 1.f - wz);
                    int idx = (Z << 14) + (Y << 7) + X;
                    f += wt * __ldg(img + idx);
                    d += wt * __ldg(opa + idx);
                }
            }
        }
    }
}

// -------- per-(ray,segment) rendering --------
// grid: (NSEG, 128 rows), block: 128 threads (one per pixel column w)
__global__ void __launch_bounds__(128)
render_kernel(const float* __restrict__ img, const float* __restrict__ opa,
              const float* __restrict__ Rm, const float* __restrict__ Tv) {
    int w = threadIdx.x;
    int seg = blockIdx.x;
    int h = blockIdx.y;

    // NDC grid: xs = linspace(1,-1,128) over w; ys likewise over h
    float gx = 1.f + (float)w * (-2.f / 127.f);
    float gy = 1.f + (float)h * (-2.f / 127.f);
    const float INV_FOCAL = 1.f / 1.7320508f;
    float dc0 = gx * INV_FOCAL, dc1 = gy * INV_FOCAL;  // dc2 = 1

    float R00 = Rm[0], R01 = Rm[1], R02 = Rm[2];
    float R10 = Rm[3], R11 = Rm[4], R12 = Rm[5];
    float R20 = Rm[6], R21 = Rm[7], R22 = Rm[8];
    float T0 = Tv[0], T1 = Tv[1], T2 = Tv[2];

    // dirs_world[j] = sum_i dirs_cam[i] * R[j][i]
    float dwx = dc0 * R00 + dc1 * R01 + R02;
    float dwy = dc0 * R10 + dc1 * R11 + R12;
    float dwz = dc0 * R20 + dc1 * R21 + R22;
    // origin[j] = sum_i (-T[i]) * R[j][i]
    float ox = -(T0 * R00 + T1 * R01 + T2 * R02);
    float oy = -(T0 * R10 + T1 * R11 + T2 * R12);
    float oz = -(T0 * R20 + T1 * R21 + T2 * R22);

    // sample coord: fx = ((pos/half_extent)+1)*0.5*127 = pos*s + 63.5
    const float HE = 1.48828125f;  // (3/128)*127/2
    const float s = 63.5f / HE;
    float ax = dwx * s, bx = ox * s + 63.5f;
    float ay = dwy * s, by = oy * s + 63.5f;
    float az = dwz * s, bz = oz * s + 63.5f;

    float Tt = 1.f, acc = 0.f;
    int p0 = seg * PTS_PER_SEG;

#pragma unroll
    for (int g = 0; g < PTS_PER_SEG / 4; g++) {
        float fv[4], dv[4];
#pragma unroll
        for (int k = 0; k < 4; k++) {
            int p = p0 + g * 4 + k;
            float depth = 2.f + (float)p * (4.f / 255.f);
            tri_sample(img, opa, ax * depth + bx, ay * depth + by,
                       az * depth + bz, fv[k], dv[k]);
            dv[k] *= 0.1f;  // densities = opacity * SCALING
        }
#pragma unroll
        for (int k = 0; k < 4; k++) {
            // (1.0 + 1e-10) == 1.0f in fp32 (matches JAX fp32 trace)
            acc += fv[k] * dv[k] * Tt;
            Tt *= (1.f - dv[k]);
        }
    }

    int r = h * 128 + w;
    g_acc[seg * NRAYS + r] = acc;
    g_prodv[seg * NRAYS + r] = Tt;
}

// -------- fused: combine segments + global stats + normalize + reset ------
// grid: 64 blocks x 256 threads; last-arriving block finalizes.
__global__ void __launch_bounds__(256) combine_finalize_kernel(float* __restrict__ out) {
    int r = blockIdx.x * blockDim.x + threadIdx.x;
    float gray = 0.f;
    float Tt = 1.f;
#pragma unroll
    for (int s2 = 0; s2 < NSEG; s2++) {
        gray += g_acc[s2 * NRAYS + r] * Tt;
        Tt *= g_prodv[s2 * NRAYS + r];
    }
    g_gray[r] = gray;

    // block reduction: sum, sumsq (double), min, max
    double sm = (double)gray;
    double sq = (double)gray * (double)gray;
    float mn = gray, mx = gray;
#pragma unroll
    for (int off = 16; off > 0; off >>= 1) {
        sm += __shfl_down_sync(0xFFFFFFFFu, sm, off);
        sq += __shfl_down_sync(0xFFFFFFFFu, sq, off);
        mn = fminf(mn, __shfl_down_sync(0xFFFFFFFFu, mn, off));
        mx = fmaxf(mx, __shfl_down_sync(0xFFFFFFFFu, mx, off));
    }
    __shared__ double s_sm[8], s_sq[8];
    __shared__ float s_mn[8], s_mx[8];
    int lane = threadIdx.x & 31, wid = threadIdx.x >> 5;
    if (lane == 0) {
        s_sm[wid] = sm;
        s_sq[wid] = sq;
        s_mn[wid] = mn;
        s_mx[wid] = mx;
    }
    __syncthreads();
    if (wid == 0) {
        sm = (lane < 8) ? s_sm[lane] : 0.0;
        sq = (lane < 8) ? s_sq[lane] : 0.0;
        mn = (lane < 8) ? s_mn[lane] : 3.0e38f;
        mx = (lane < 8) ? s_mx[lane] : -3.0e38f;
#pragma unroll
        for (int off = 4; off > 0; off >>= 1) {
            sm += __shfl_down_sync(0xFFFFFFFFu, sm, off);
            sq += __shfl_down_sync(0xFFFFFFFFu, sq, off);
            mn = fminf(mn, __shfl_down_sync(0xFFFFFFFFu, mn, off));
            mx = fmaxf(mx, __shfl_down_sync(0xFFFFFFFFu, mx, off));
        }
        if (lane == 0) {
            atomicAdd(&g_sum, sm);
            atomicAdd(&g_sumsq, sq);
            atomicMin(&g_minkey, fkey(mn));
            atomicMax(&g_maxkey, fkey(mx));
        }
    }

    // last-block-arrives: finalize + reset scratch for next graph replay
    __threadfence();
    __shared__ bool is_last;
    __shared__ float sh_mean, sh_inv, sh_stmin, sh_stmax;
    if (threadIdx.x == 0) {
        unsigned c = atomicAdd(&g_count, 1u);
        is_last = (c == 63u);
    }
    __syncthreads();
    if (!is_last) return;

    if (threadIdx.x == 0) {
        double sum = *(volatile double*)&g_sum;
        double sumsq = *(volatile double*)&g_sumsq;
        unsigned mnk = *(volatile unsigned*)&g_minkey;
        unsigned mxk = *(volatile unsigned*)&g_maxkey;
        double mean = sum / 16384.0;
        double var = (sumsq - sum * sum / 16384.0) / 16383.0;
        float stddev = (float)sqrt(var > 0.0 ? var : 0.0);
        float gmin = funkey(mnk), gmax = funkey(mxk);
        float fmean = (float)mean;
        float inv = 1.f / (stddev + 1e-8f);
        sh_mean = fmean;
        sh_inv = inv;
        sh_stmin = (gmin - fmean) * inv;
        sh_stmax = (gmax - fmean) * inv;
        // reset scratch to module-load state for the next replay
        g_sum = 0.0;
        g_sumsq = 0.0;
        g_minkey = 0xFFFFFFFFu;
        g_maxkey = 0u;
        g_count = 0u;
    }
    __syncthreads();

    float fmean = sh_mean, inv = sh_inv;
    float stmin = sh_stmin, stmax = sh_stmax;
    float rng = 1.f / (stmax - stmin + 1e-8f);

    // Output with per-warp 32x32 smem tile transpose (conflict-free, coalesced
    // both directions). out layout [1,1,W,H]: out[w*128+h] = gray(h,w).
    __shared__ float tile[8][32 * 33];
    // 16 tiles (4x4 grid of 32x32); 8 warps -> 2 tiles each
    for (int t = wid; t < 16; t += 8) {
        int th = (t >> 2) * 32;  // tile origin in h
        int tw = (t & 3) * 32;   // tile origin in w
        float* sm_t = tile[wid];
        __syncwarp();
#pragma unroll
        for (int rr = 0; rr < 32; rr++) {
            // coalesced read: row (th+rr), cols tw+lane
            float v = g_gray[(th + rr) * 128 + tw + lane];
            float vn = (v - fmean) * inv;
            sm_t[rr * 33 + lane] = (vn - stmin + 1e-8f) * rng;
        }
        __syncwarp();
#pragma unroll
        for (int rr = 0; rr < 32; rr++) {
            // coalesced write: out row (tw+rr), cols th+lane
            // out[(tw+rr)*128 + th+lane] = gray[(th+lane)*128 + (tw+rr)]
            out[(tw + rr) * 128 + th + lane] = sm_t[lane * 33 + rr];
        }
    }
}

extern "C" void kernel_launch(void* const* d_in, const int* in_sizes, int n_in,
                              void* d_out, int out_size) {
    const float* img = (const float*)d_in[0];  // image3d [1,1,128,128,128]
    const float* opa = (const float*)d_in[1];  // opacity  [1,1,128,128,128]
    const float* Rm = (const float*)d_in[2];   // R [1,3,3]
    const float* Tv = (const float*)d_in[3];   // T [1,3]
    float* out = (float*)d_out;                // [1,1,128,128]

    render_kernel<<<dim3(NSEG, IMG_DIM), 128>>>(img, opa, Rm, Tv);
    combine_finalize_kernel<<<64, 256>>>(out);
}

// round 7
// speedup vs baseline: 2.0771x; 1.0128x over previous
#include <cuda_runtime.h>
#include <math.h>

#define NRAYS 16384
#define NSEG 16
#define PTS_PER_SEG 16
#define IMG_DIM 128

// -------- device scratch (no allocations allowed) --------
__device__ float2 g_seg[NSEG * NRAYS];  // (acc, transmittance) per ray-segment
__device__ float g_gray[NRAYS];
// Initializers are load-bearing: the first invocation reads these, and the
// last finalize block resets them to the same values for replay.
__device__ double g_sum = 0.0, g_sumsq = 0.0;
__device__ unsigned g_minkey = 0xFFFFFFFFu;
__device__ unsigned g_maxkey = 0u;
__device__ unsigned g_count = 0u;

// -------- ordered-float key for atomicMin/Max --------
__device__ __forceinline__ unsigned fkey(float f) {
    unsigned u = __float_as_uint(f);
    return (u & 0x80000000u) ? ~u : (u | 0x80000000u);
}
__device__ __forceinline__ float funkey(unsigned k) {
    return (k & 0x80000000u) ? __uint_as_float(k & 0x7FFFFFFFu)
                             : __uint_as_float(~k);
}

// -------- trilinear sample of both volumes (zero padding outside) --------
__device__ __forceinline__ void tri_sample(const float* __restrict__ img,
                                           const float* __restrict__ opa,
                                           float fx, float fy, float fz,
                                           float& f, float& d) {
    float x0 = floorf(fx), y0 = floorf(fy), z0 = floorf(fz);
    int ix = (int)x0, iy = (int)y0, iz = (int)z0;
    float wx = fx - x0, wy = fy - y0, wz = fz - z0;
    f = 0.f;
    d = 0.f;
#pragma unroll
    for (int dz = 0; dz < 2; dz++) {
#pragma unroll
        for (int dy = 0; dy < 2; dy++) {
#pragma unroll
            for (int dx = 0; dx < 2; dx++) {
                int X = ix + dx, Y = iy + dy, Z = iz + dz;
                if ((unsigned)X < 128u && (unsigned)Y < 128u && (unsigned)Z < 128u) {
                    float wt = (dx ? wx : 1.f - wx) * (dy ? wy : 1.f - wy) *
                               (dz ? wz : 1.f - wz);
                    int idx = (Z << 14) + (Y << 7) + X;
                    f += wt * __ldg(img + idx);
                    d += wt * __ldg(opa + idx);
                }
            }
        }
    }
}

// -------- per-(ray,segment) rendering --------
// grid: (NSEG, 128 rows), block: 128 threads (one per pixel column w)
__global__ void __launch_bounds__(128)
render_kernel(const float* __restrict__ img, const float* __restrict__ opa,
              const float* __restrict__ Rm, const float* __restrict__ Tv) {
    int w = threadIdx.x;
    int seg = blockIdx.x;
    int h = blockIdx.y;

    // NDC grid: xs = linspace(1,-1,128) over w; ys likewise over h
    float gx = 1.f + (float)w * (-2.f / 127.f);
    float gy = 1.f + (float)h * (-2.f / 127.f);
    const float INV_FOCAL = 1.f / 1.7320508f;
    float dc0 = gx * INV_FOCAL, dc1 = gy * INV_FOCAL;  // dc2 = 1

    float R00 = Rm[0], R01 = Rm[1], R02 = Rm[2];
    float R10 = Rm[3], R11 = Rm[4], R12 = Rm[5];
    float R20 = Rm[6], R21 = Rm[7], R22 = Rm[8];
    float T0 = Tv[0], T1 = Tv[1], T2 = Tv[2];

    // dirs_world[j] = sum_i dirs_cam[i] * R[j][i]
    float dwx = dc0 * R00 + dc1 * R01 + R02;
    float dwy = dc0 * R10 + dc1 * R11 + R12;
    float dwz = dc0 * R20 + dc1 * R21 + R22;
    // origin[j] = sum_i (-T[i]) * R[j][i]
    float ox = -(T0 * R00 + T1 * R01 + T2 * R02);
    float oy = -(T0 * R10 + T1 * R11 + T2 * R12);
    float oz = -(T0 * R20 + T1 * R21 + T2 * R22);

    // sample coord: fx = ((pos/half_extent)+1)*0.5*127 = pos*s + 63.5
    const float HE = 1.48828125f;  // (3/128)*127/2
    const float s = 63.5f / HE;
    float ax = dwx * s, bx = ox * s + 63.5f;
    float ay = dwy * s, by = oy * s + 63.5f;
    float az = dwz * s, bz = oz * s + 63.5f;

    float Tt = 1.f, acc = 0.f;
    int p0 = seg * PTS_PER_SEG;

#pragma unroll
    for (int g = 0; g < PTS_PER_SEG / 4; g++) {
        float fv[4], dv[4];
#pragma unroll
        for (int k = 0; k < 4; k++) {
            int p = p0 + g * 4 + k;
            float depth = 2.f + (float)p * (4.f / 255.f);
            tri_sample(img, opa, ax * depth + bx, ay * depth + by,
                       az * depth + bz, fv[k], dv[k]);
            dv[k] *= 0.1f;  // densities = opacity * SCALING
        }
#pragma unroll
        for (int k = 0; k < 4; k++) {
            // (1.0 + 1e-10) == 1.0f in fp32 (matches JAX fp32 trace)
            acc += fv[k] * dv[k] * Tt;
            Tt *= (1.f - dv[k]);
        }
    }

    int r = h * 128 + w;
    g_seg[seg * NRAYS + r] = make_float2(acc, Tt);
}

// -------- combine segments + accumulate global stats (64 blocks x 256) ----
__global__ void __launch_bounds__(256) combine_stats_kernel() {
    int r = blockIdx.x * blockDim.x + threadIdx.x;
    float gray = 0.f;
    float Tt = 1.f;
#pragma unroll
    for (int s2 = 0; s2 < NSEG; s2++) {
        float2 v = g_seg[s2 * NRAYS + r];
        gray += v.x * Tt;
        Tt *= v.y;
    }
    g_gray[r] = gray;

    // block reduction: sum, sumsq (double), min, max
    double sm = (double)gray;
    double sq = (double)gray * (double)gray;
    float mn = gray, mx = gray;
#pragma unroll
    for (int off = 16; off > 0; off >>= 1) {
        sm += __shfl_down_sync(0xFFFFFFFFu, sm, off);
        sq += __shfl_down_sync(0xFFFFFFFFu, sq, off);
        mn = fminf(mn, __shfl_down_sync(0xFFFFFFFFu, mn, off));
        mx = fmaxf(mx, __shfl_down_sync(0xFFFFFFFFu, mx, off));
    }
    __shared__ double s_sm[8], s_sq[8];
    __shared__ float s_mn[8], s_mx[8];
    int lane = threadIdx.x & 31, wid = threadIdx.x >> 5;
    if (lane == 0) {
        s_sm[wid] = sm;
        s_sq[wid] = sq;
        s_mn[wid] = mn;
        s_mx[wid] = mx;
    }
    __syncthreads();
    if (wid == 0) {
        sm = (lane < 8) ? s_sm[lane] : 0.0;
        sq = (lane < 8) ? s_sq[lane] : 0.0;
        mn = (lane < 8) ? s_mn[lane] : 3.0e38f;
        mx = (lane < 8) ? s_mx[lane] : -3.0e38f;
#pragma unroll
        for (int off = 4; off > 0; off >>= 1) {
            sm += __shfl_down_sync(0xFFFFFFFFu, sm, off);
            sq += __shfl_down_sync(0xFFFFFFFFu, sq, off);
            mn = fminf(mn, __shfl_down_sync(0xFFFFFFFFu, mn, off));
            mx = fmaxf(mx, __shfl_down_sync(0xFFFFFFFFu, mx, off));
        }
        if (lane == 0) {
            atomicAdd(&g_sum, sm);
            atomicAdd(&g_sumsq, sq);
            atomicMin(&g_minkey, fkey(mn));
            atomicMax(&g_maxkey, fkey(mx));
        }
    }
    // no fence / no tail: the kernel boundary orders these atomics before
    // finalize_kernel's reads.
}

// -------- parallel normalize + transpose (16 blocks x 256, one tile each) --
__global__ void __launch_bounds__(256) finalize_kernel(float* __restrict__ out) {
    // every block derives the scalars redundantly (broadcast loads, cheap)
    double sum = g_sum, sumsq = g_sumsq;
    double mean = sum / 16384.0;
    double var = (sumsq - sum * sum / 16384.0) / 16383.0;
    float stddev = (float)sqrt(var > 0.0 ? var : 0.0);
    float gmin = funkey(g_minkey), gmax = funkey(g_maxkey);
    float fmean = (float)mean;
    float inv = 1.f / (stddev + 1e-8f);
    float stmin = (gmin - fmean) * inv;
    float stmax = (gmax - fmean) * inv;
    float rng = 1.f / (stmax - stmin + 1e-8f);

    // 32x32 tile transpose: out[w*128+h] = norm(gray[h*128+w])
    __shared__ float tile[32 * 33];
    int lane = threadIdx.x & 31, wid = threadIdx.x >> 5;
    int th = (blockIdx.x >> 2) * 32;  // tile origin in h
    int tw = (blockIdx.x & 3) * 32;   // tile origin in w
#pragma unroll
    for (int i = 0; i < 4; i++) {
        int rr = wid * 4 + i;
        float v = g_gray[(th + rr) * 128 + tw + lane];
        float vn = (v - fmean) * inv;
        tile[rr * 33 + lane] = (vn - stmin + 1e-8f) * rng;
    }
    __syncthreads();
#pragma unroll
    for (int i = 0; i < 4; i++) {
        int rr = wid * 4 + i;
        out[(tw + rr) * 128 + th + lane] = tile[lane * 33 + rr];
    }

    // last-arriving block resets scratch to module-load state for replay.
    // All blocks read the stats globals before incrementing, so the reset
    // cannot race any reader.
    __threadfence();
    if (threadIdx.x == 0) {
        unsigned c = atomicAdd(&g_count, 1u);
        if (c == 15u) {
            g_sum = 0.0;
            g_sumsq = 0.0;
            g_minkey = 0xFFFFFFFFu;
            g_maxkey = 0u;
            g_count = 0u;
        }
    }
}

extern "C" void kernel_launch(void* const* d_in, const int* in_sizes, int n_in,
                              void* d_out, int out_size) {
    const float* img = (const float*)d_in[0];  // image3d [1,1,128,128,128]
    const float* opa = (const float*)d_in[1];  // opacity  [1,1,128,128,128]
    const float* Rm = (const float*)d_in[2];   // R [1,3,3]
    const float* Tv = (const float*)d_in[3];   // T [1,3]
    float* out = (float*)d_out;                // [1,1,128,128]

    render_kernel<<<dim3(NSEG, IMG_DIM), 128>>>(img, opa, Rm, Tv);
    combine_stats_kernel<<<64, 256>>>();
    finalize_kernel<<<16, 256>>>(out);
}